// round 15
// baseline (speedup 1.0000x reference)
#include <cuda_runtime.h>

// DRNN: two stacked SimpleRNN(tanh), round 12. B=512, T=512, D=64, H=100.
//
// Kernel 1 (xp_prepass v5): XP[b,t,u] = x_{b,t}.W1x[:,u] + b1[u].
//   v4's register-tiled compute (4t x 5u per thread, 9 LDS.128 -> 40 FFMA2
//   per k-quad, 20 indep acc chains) + FIXED epilogue: results staged into
//   smem (reusing the dead W tile) then written as flat coalesced STG.128.
//   v4's 6x-amplified scattered stores were the 278us regression.
//   320 thr, grid (8, 512), 2 CTAs/SM.
//
// Kernel 2 (mainloop): UNCHANGED (proven 625us): 128 CTAs x 4 rows, 256
//   thr, all warps 2 units/lane (100 u64 wregs), 600 LDS/step, per-SMSP
//   exactly 600 FFMA2 (balanced 1200-cyc floor):
//   G1 (wid 0-3) row-split 2 rows/warp; G2a (wid 4,5); G2b (wid 6,7).
//   Pairwise named barriers bar2 (G1+G2a), bar3 (G2a+G2b).

#define TT   512
#define BB   512
#define DD   64
#define HH   100
#define ROWS 4
#define HSR  104    // h/p row stride
#define NTHR 256
#define XPAD 68     // prepass x-tile row stride (272B: conflict-free)

#define BAR_SYNC(id, cnt) asm volatile("bar.sync %0, %1;" :: "r"(id), "r"(cnt) : "memory")

__device__ float XPbuf[(size_t)BB * TT * HH];   // 104.8 MB scratch

__device__ __forceinline__ void ffma2(unsigned long long &acc,
                                      unsigned long long a,
                                      unsigned long long b) {
    asm("fma.rn.f32x2 %0, %1, %2, %0;" : "+l"(acc) : "l"(a), "l"(b));
}

__device__ __forceinline__ unsigned long long pack2(float lo, float hi) {
    unsigned long long r;
    asm("mov.b64 %0, {%1, %2};" : "=l"(r) : "f"(lo), "f"(hi));
    return r;
}

__device__ __forceinline__ float hsum2(unsigned long long v) {
    float lo, hi;
    asm("mov.b64 {%0, %1}, %2;" : "=f"(lo), "=f"(hi) : "l"(v));
    return lo + hi;
}

__device__ __forceinline__ ulonglong2 lds128(const float* p) {
    return *reinterpret_cast<const ulonglong2*>(p);
}

// tanh via exp + fast divide: ~1e-7 rel err.
__device__ __forceinline__ float tanh_f(float x) {
    float ax = fabsf(x);
    float e  = __expf(-2.0f * ax);
    float r  = __fdividef(1.0f - e, 1.0f + e);
    return copysignf(r, x);
}

// ───────────────────────── Kernel 1: XP pre-pass v5 ──────────────────────
// grid (8, 512): blockIdx.x = 64-timestep tile, blockIdx.y = batch row.
// 320 thr: tb = tid&15 -> 4 timesteps; ub = tid>>4 -> 5 units.
// Epilogue: stage [64][100] result in smem (reuse W region), then flat
// coalesced float4 writes to XPbuf.
__global__ __launch_bounds__(320, 2)
void xp_prepass(const float* __restrict__ X, const float* __restrict__ W1x,
                const float* __restrict__ B1)
{
    __shared__ __align__(16) float sW [HH * DD];   // W1x [u][k]; reused as out
    __shared__ __align__(16) float sXT[64][XPAD];  // x tile, padded rows

    const int b   = blockIdx.y;
    const int t0  = blockIdx.x * 64;
    const int tid = threadIdx.x;
    const int tb  = tid & 15;
    const int ub  = tid >> 4;                      // 0..19
    const int u_base = ub * 5;                     // 0,5,...,95

    // Load W transposed: 6400 floats, 20 per thread (L2-cached broadcast).
    for (int idx = tid; idx < HH * DD; idx += 320)
        sW[idx] = W1x[(idx & 63) * HH + (idx >> 6)];
    // Load x tile: 64 t x 64 k, float4, padded smem rows.
    for (int idx = tid; idx < 64 * 16; idx += 320) {
        int t = idx >> 4, q = idx & 15;
        float4 v = reinterpret_cast<const float4*>(
            X + ((size_t)b * TT + t0) * DD)[idx];
        *reinterpret_cast<float4*>(&sXT[t][q * 4]) = v;
    }
    __syncthreads();

    unsigned long long acc[4][5];
    #pragma unroll
    for (int i = 0; i < 4; ++i)
        #pragma unroll
        for (int j = 0; j < 5; ++j) acc[i][j] = 0ull;

    #pragma unroll
    for (int kq = 0; kq < 16; ++kq) {
        ulonglong2 xv[4];
        #pragma unroll
        for (int i = 0; i < 4; ++i)
            xv[i] = lds128(&sXT[tb * 4 + i][kq * 4]);
        ulonglong2 wv[5];
        #pragma unroll
        for (int j = 0; j < 5; ++j)
            wv[j] = lds128(&sW[(u_base + j) * DD + kq * 4]);
        #pragma unroll
        for (int i = 0; i < 4; ++i) {
            #pragma unroll
            for (int j = 0; j < 5; ++j) {
                ffma2(acc[i][j], xv[i].x, wv[j].x);
                ffma2(acc[i][j], xv[i].y, wv[j].y);
            }
        }
    }

    float bj[5];
    #pragma unroll
    for (int j = 0; j < 5; ++j) bj[j] = B1[u_base + j];

    // Stage results into smem (W region is dead now).
    __syncthreads();                               // all W reads done
    float* sOut = sW;                              // [64][100] flat
    #pragma unroll
    for (int i = 0; i < 4; ++i) {
        #pragma unroll
        for (int j = 0; j < 5; ++j)
            sOut[(tb * 4 + i) * HH + u_base + j] = hsum2(acc[i][j]) + bj[j];
    }
    __syncthreads();

    // Coalesced flat copy: 6400 floats = 1600 float4, 5 per thread.
    // Dst offset (b*TT + t0)*HH is a multiple of 4 -> 16B aligned.
    {
        float4* dst = reinterpret_cast<float4*>(
            &XPbuf[((size_t)b * TT + t0) * HH]);
        const float4* src = reinterpret_cast<const float4*>(sOut);
        #pragma unroll
        for (int s = 0; s < 5; ++s)
            dst[tid + 320 * s] = src[tid + 320 * s];
    }
}

// ───────────────────────── Kernel 2: main recurrence (unchanged) ─────────

// G2 accumulate: 4 rows x 2 units. acc[r]=unit0, acc[4+r]=unit1.
__device__ __forceinline__ void accum8_h(unsigned long long (&acc)[8],
                                         const float* base,
                                         const unsigned long long* w)
{
    #pragma unroll
    for (int it = 0; it < 25; ++it) {
        ulonglong2 v0 = lds128(base + 0*HSR + 4*it);
        ulonglong2 v1 = lds128(base + 1*HSR + 4*it);
        ulonglong2 v2 = lds128(base + 2*HSR + 4*it);
        ulonglong2 v3 = lds128(base + 3*HSR + 4*it);
        unsigned long long wA0 = w[4*it + 0];
        unsigned long long wB0 = w[4*it + 1];
        unsigned long long wA1 = w[4*it + 2];
        unsigned long long wB1 = w[4*it + 3];
        ffma2(acc[0], v0.x, wA0); ffma2(acc[4], v0.x, wA1);
        ffma2(acc[1], v1.x, wA0); ffma2(acc[5], v1.x, wA1);
        ffma2(acc[2], v2.x, wA0); ffma2(acc[6], v2.x, wA1);
        ffma2(acc[3], v3.x, wA0); ffma2(acc[7], v3.x, wA1);
        ffma2(acc[0], v0.y, wB0); ffma2(acc[4], v0.y, wB1);
        ffma2(acc[1], v1.y, wB0); ffma2(acc[5], v1.y, wB1);
        ffma2(acc[2], v2.y, wB0); ffma2(acc[6], v2.y, wB1);
        ffma2(acc[3], v3.y, wB0); ffma2(acc[7], v3.y, wB1);
    }
}

// G1 accumulate: 2 rows x 2 units. acc = {r0u0, r1u0, r0u1, r1u1}.
__device__ __forceinline__ void accum4_g1(unsigned long long (&acc)[4],
                                          const float* base,
                                          const unsigned long long* w)
{
    #pragma unroll
    for (int it = 0; it < 25; ++it) {
        ulonglong2 v0 = lds128(base + 0*HSR + 4*it);
        ulonglong2 v1 = lds128(base + 1*HSR + 4*it);
        unsigned long long wA0 = w[4*it + 0];
        unsigned long long wB0 = w[4*it + 1];
        unsigned long long wA1 = w[4*it + 2];
        unsigned long long wB1 = w[4*it + 3];
        ffma2(acc[0], v0.x, wA0); ffma2(acc[1], v1.x, wA0);
        ffma2(acc[2], v0.x, wA1); ffma2(acc[3], v1.x, wA1);
        ffma2(acc[0], v0.y, wB0); ffma2(acc[1], v1.y, wB0);
        ffma2(acc[2], v0.y, wB1); ffma2(acc[3], v1.y, wB1);
    }
}

__global__ __launch_bounds__(NTHR, 1)
void drnn_kernel(const float* __restrict__ W1h,
                 const float* __restrict__ W2x, const float* __restrict__ W2h,
                 const float* __restrict__ B2,
                 const float* __restrict__ Wo,  const float* __restrict__ Bo,
                 float* __restrict__ out)
{
    __shared__ __align__(16) float sH1[2][ROWS][HSR];
    __shared__ __align__(16) float sH2[2][ROWS][HSR];
    __shared__ __align__(16) float sP [2][ROWS][HSR];   // p = W2x.h1 + b2

    const int tid  = threadIdx.x;
    const int wid  = tid >> 5;
    const int lane = tid & 31;
    const int r0   = blockIdx.x * ROWS;
    const int gid  = (wid < 4) ? 0 : ((wid < 6) ? 1 : 2);
    const int uh   = wid & 1;
    const int u0r  = uh * 64 + 2 * lane;
    const bool act = (u0r < HH);
    const int u0   = act ? u0r : (HH - 2);
    const int rp   = (wid >> 1) & 1;

    unsigned long long w[100];
    float bj0 = 0.f, bj1 = 0.f;
    {
        const float* Wsrc = (gid == 0) ? W1h : ((gid == 1) ? W2x : W2h);
        #pragma unroll
        for (int q = 0; q < 25; ++q) {
            int k = 4 * q;
            w[4*q+0] = pack2(Wsrc[(k  )*HH + u0  ], Wsrc[(k+1)*HH + u0  ]);
            w[4*q+1] = pack2(Wsrc[(k+2)*HH + u0  ], Wsrc[(k+3)*HH + u0  ]);
            w[4*q+2] = pack2(Wsrc[(k  )*HH + u0+1], Wsrc[(k+1)*HH + u0+1]);
            w[4*q+3] = pack2(Wsrc[(k+2)*HH + u0+1], Wsrc[(k+3)*HH + u0+1]);
        }
        if (gid == 1) { bj0 = B2[u0]; bj1 = B2[u0 + 1]; }
    }

    {
        float* z1 = &sH1[0][0][0];
        for (int idx = tid; idx < 2*ROWS*HSR; idx += NTHR) z1[idx] = 0.f;
        float* z2 = &sH2[0][0][0];
        for (int idx = tid; idx < 2*ROWS*HSR; idx += NTHR) z2[idx] = 0.f;
    }
    __syncthreads();

    float2 xcur[2];
    if (gid == 0) {
        #pragma unroll
        for (int r = 0; r < 2; ++r)
            xcur[r] = *reinterpret_cast<const float2*>(
                &XPbuf[((size_t)(r0 + rp*2 + r) * TT + 0) * HH + u0]);
    }

    for (int i = 0; i <= TT + 1; ++i) {
        const int pc = i & 1, pn = pc ^ 1;
        if (gid == 0) {
            if (i <= TT - 1) {                           // h1_i (2 rows)
                float2 xn[2];
                const bool pf = (i + 1 <= TT - 1);
                if (pf) {
                    #pragma unroll
                    for (int r = 0; r < 2; ++r)
                        xn[r] = *reinterpret_cast<const float2*>(
                            &XPbuf[((size_t)(r0 + rp*2 + r) * TT + (i+1)) * HH + u0]);
                }
                unsigned long long a[4] = {0ull, 0ull, 0ull, 0ull};
                accum4_g1(a, &sH1[pn][rp*2][0], w);
                if (act) {
                    float2 o0, o1;
                    o0.x = tanh_f(hsum2(a[0]) + xcur[0].x);
                    o0.y = tanh_f(hsum2(a[2]) + xcur[0].y);
                    o1.x = tanh_f(hsum2(a[1]) + xcur[1].x);
                    o1.y = tanh_f(hsum2(a[3]) + xcur[1].y);
                    *reinterpret_cast<float2*>(&sH1[pc][rp*2    ][u0]) = o0;
                    *reinterpret_cast<float2*>(&sH1[pc][rp*2 + 1][u0]) = o1;
                }
                if (pf) { xcur[0] = xn[0]; xcur[1] = xn[1]; }
            }
            BAR_SYNC(2, 192);
        } else if (gid == 1) {
            if (i >= 1 && i <= TT) {                     // p_{i-1} (4 rows)
                unsigned long long a[8];
                #pragma unroll
                for (int n = 0; n < 8; ++n) a[n] = 0ull;
                accum8_h(a, &sH1[pn][0][0], w);
                if (act) {
                    #pragma unroll
                    for (int r = 0; r < ROWS; ++r) {
                        float2 v;
                        v.x = hsum2(a[r])   + bj0;
                        v.y = hsum2(a[4+r]) + bj1;
                        *reinterpret_cast<float2*>(&sP[pn][r][u0]) = v;
                    }
                }
            }
            BAR_SYNC(3, 128);
            BAR_SYNC(2, 192);
        } else {
            if (i >= 2) {                                // h2_{i-2} (4 rows)
                float2 pv[4];
                #pragma unroll
                for (int r = 0; r < ROWS; ++r)
                    pv[r] = *reinterpret_cast<const float2*>(&sP[pc][r][u0]);
                unsigned long long a[8];
                #pragma unroll
                for (int n = 0; n < 8; ++n) a[n] = 0ull;
                accum8_h(a, &sH2[pn][0][0], w);
                if (act) {
                    #pragma unroll
                    for (int r = 0; r < ROWS; ++r) {
                        float2 v;
                        v.x = tanh_f(hsum2(a[r])   + pv[r].x);
                        v.y = tanh_f(hsum2(a[4+r]) + pv[r].y);
                        *reinterpret_cast<float2*>(&sH2[pc][r][u0]) = v;
                    }
                }
            }
            BAR_SYNC(3, 128);
        }
    }
    __syncthreads();

    float* outVec = out;                      // [512]
    float* outH1  = out + BB;                 // [512,100]
    float* outH2  = out + BB + BB*HH;         // [512,100]

    for (int idx = tid; idx < ROWS*HH; idx += NTHR) {
        int r = idx / HH, uu = idx % HH;
        outH1[(size_t)(r0 + r)*HH + uu] = sH1[1][r][uu];
        outH2[(size_t)(r0 + r)*HH + uu] = sH2[1][r][uu];
    }

    if (tid < 32) {
        #pragma unroll
        for (int r = 0; r < ROWS; ++r) {
            float v = 0.f;
            #pragma unroll
            for (int mm = 0; mm < 4; ++mm) {
                int uu = mm*32 + tid;
                if (uu < HH) v += sH2[1][r][uu] * Wo[uu];
            }
            #pragma unroll
            for (int off = 16; off; off >>= 1)
                v += __shfl_down_sync(0xffffffffu, v, off);
            if (tid == 0) outVec[r0 + r] = v + Bo[0];
        }
    }
}

extern "C" void kernel_launch(void* const* d_in, const int* in_sizes, int n_in,
                              void* d_out, int out_size) {
    (void)in_sizes; (void)n_in; (void)out_size;
    const float* X   = (const float*)d_in[0];
    const float* W1x = (const float*)d_in[1];
    const float* W1h = (const float*)d_in[2];
    const float* B1  = (const float*)d_in[3];
    const float* W2x = (const float*)d_in[4];
    const float* W2h = (const float*)d_in[5];
    const float* B2  = (const float*)d_in[6];
    const float* Wo  = (const float*)d_in[7];
    const float* Bo  = (const float*)d_in[8];

    dim3 pgrid(8, BB);
    xp_prepass<<<pgrid, 320>>>(X, W1x, B1);
    drnn_kernel<<<BB/ROWS, NTHR>>>(W1h, W2x, W2h, B2, Wo, Bo, (float*)d_out);
}

// round 16
// speedup vs baseline: 1.0547x; 1.0547x over previous
#include <cuda_runtime.h>

// DRNN: two stacked SimpleRNN(tanh), round 13. B=512, T=512, D=64, H=100.
// SINGLE persistent kernel, 128 CTAs x 4 rows, 256 threads.
//
// Phase 0 (per-CTA XP prepass, fused): XP[b][u][t] = x_{b,t}.W1x[:,u]+b1[u]
//   for the CTA's own 4 rows (no grid sync needed - each CTA reads only its
//   own slice). Register-tiled 4t x 7u per thread (28 indep acc chains,
//   11 LDS.128 -> 56 FFMA2 per k-quad). t-INTERLEAVED lanes (t = tb + 16i):
//   lane t-stride 1 -> smem word-stride 68 === 4 (mod 32) -> conflict-free
//   (v4/v5's row-blocked lanes had 4-way conflicts). No occupancy cap ->
//   no register spills (v4/v5's 100-reg cap was the real 258us regression).
//   XPbuf is [b][u][t]: phase-0 stores coalesce per-u; recurrence reads
//   become sequential-in-t streams (L1-friendly).
//
// Phase 1 (recurrence): UNCHANGED proven 625us structure: all warps
//   2 units/lane (100 u64 wregs), 600 LDS/step, 600 FFMA2/SMSP (balanced):
//   G1 (wid 0-3) row-split 2 rows/warp; G2a (wid 4,5); G2b (wid 6,7).
//   Pairwise named barriers bar2 (G1+G2a), bar3 (G2a+G2b).
// Shared memory overlaid: phase0 uses 42KB (sW+sXT), phase1 uses 10KB rings.

#define TT   512
#define BB   512
#define DD   64
#define HH   100
#define ROWS 4
#define HSR  104    // h/p ring row stride (floats)
#define NTHR 256
#define XPAD 68     // phase-0 x-tile row stride (68 = 4 mod 32 banks w/ t-interleave)

#define BAR_SYNC(id, cnt) asm volatile("bar.sync %0, %1;" :: "r"(id), "r"(cnt) : "memory")

__device__ float XPbuf[(size_t)BB * HH * TT];   // [b][u][t], 104.8 MB

__device__ __forceinline__ void ffma2(unsigned long long &acc,
                                      unsigned long long a,
                                      unsigned long long b) {
    asm("fma.rn.f32x2 %0, %1, %2, %0;" : "+l"(acc) : "l"(a), "l"(b));
}

__device__ __forceinline__ unsigned long long pack2(float lo, float hi) {
    unsigned long long r;
    asm("mov.b64 %0, {%1, %2};" : "=l"(r) : "f"(lo), "f"(hi));
    return r;
}

__device__ __forceinline__ float hsum2(unsigned long long v) {
    float lo, hi;
    asm("mov.b64 {%0, %1}, %2;" : "=f"(lo), "=f"(hi) : "l"(v));
    return lo + hi;
}

__device__ __forceinline__ ulonglong2 lds128(const float* p) {
    return *reinterpret_cast<const ulonglong2*>(p);
}

// tanh via exp + fast divide: ~1e-7 rel err.
__device__ __forceinline__ float tanh_f(float x) {
    float ax = fabsf(x);
    float e  = __expf(-2.0f * ax);
    float r  = __fdividef(1.0f - e, 1.0f + e);
    return copysignf(r, x);
}

// G2 accumulate: 4 rows x 2 units. acc[r]=unit0, acc[4+r]=unit1.
__device__ __forceinline__ void accum8_h(unsigned long long (&acc)[8],
                                         const float* base,
                                         const unsigned long long* w)
{
    #pragma unroll
    for (int it = 0; it < 25; ++it) {
        ulonglong2 v0 = lds128(base + 0*HSR + 4*it);
        ulonglong2 v1 = lds128(base + 1*HSR + 4*it);
        ulonglong2 v2 = lds128(base + 2*HSR + 4*it);
        ulonglong2 v3 = lds128(base + 3*HSR + 4*it);
        unsigned long long wA0 = w[4*it + 0];
        unsigned long long wB0 = w[4*it + 1];
        unsigned long long wA1 = w[4*it + 2];
        unsigned long long wB1 = w[4*it + 3];
        ffma2(acc[0], v0.x, wA0); ffma2(acc[4], v0.x, wA1);
        ffma2(acc[1], v1.x, wA0); ffma2(acc[5], v1.x, wA1);
        ffma2(acc[2], v2.x, wA0); ffma2(acc[6], v2.x, wA1);
        ffma2(acc[3], v3.x, wA0); ffma2(acc[7], v3.x, wA1);
        ffma2(acc[0], v0.y, wB0); ffma2(acc[4], v0.y, wB1);
        ffma2(acc[1], v1.y, wB0); ffma2(acc[5], v1.y, wB1);
        ffma2(acc[2], v2.y, wB0); ffma2(acc[6], v2.y, wB1);
        ffma2(acc[3], v3.y, wB0); ffma2(acc[7], v3.y, wB1);
    }
}

// G1 accumulate: 2 rows x 2 units. acc = {r0u0, r1u0, r0u1, r1u1}.
__device__ __forceinline__ void accum4_g1(unsigned long long (&acc)[4],
                                          const float* base,
                                          const unsigned long long* w)
{
    #pragma unroll
    for (int it = 0; it < 25; ++it) {
        ulonglong2 v0 = lds128(base + 0*HSR + 4*it);
        ulonglong2 v1 = lds128(base + 1*HSR + 4*it);
        unsigned long long wA0 = w[4*it + 0];
        unsigned long long wB0 = w[4*it + 1];
        unsigned long long wA1 = w[4*it + 2];
        unsigned long long wB1 = w[4*it + 3];
        ffma2(acc[0], v0.x, wA0); ffma2(acc[1], v1.x, wA0);
        ffma2(acc[2], v0.x, wA1); ffma2(acc[3], v1.x, wA1);
        ffma2(acc[0], v0.y, wB0); ffma2(acc[1], v1.y, wB0);
        ffma2(acc[2], v0.y, wB1); ffma2(acc[3], v1.y, wB1);
    }
}

__global__ __launch_bounds__(NTHR, 1)
void drnn_kernel(const float* __restrict__ X,
                 const float* __restrict__ W1x, const float* __restrict__ B1,
                 const float* __restrict__ W1h,
                 const float* __restrict__ W2x, const float* __restrict__ W2h,
                 const float* __restrict__ B2,
                 const float* __restrict__ Wo,  const float* __restrict__ Bo,
                 float* __restrict__ out)
{
    // Overlaid shared memory. Phase 0: sW (25600B) + sXT (17408B) = 43008B.
    // Phase 1: sH1/sH2/sP rings, 3*3328B = 9984B.
    __shared__ __align__(16) float SM[(HH * DD) + 64 * XPAD];   // 43008 B

    const int tid  = threadIdx.x;
    const int wid  = tid >> 5;
    const int lane = tid & 31;
    const int r0   = blockIdx.x * ROWS;

    // ───────────── Phase 0: XP prepass for this CTA's 4 rows ─────────────
    {
        float* sW  = SM;                       // [u][k] 100x64
        float* sXT = SM + HH * DD;             // [t][XPAD] 64 rows

        const int tb = tid & 15;               // t-lane: t = tb + 16*i
        const int ub = tid >> 4;               // 0..15
        const int u_base = (ub * 7 <= HH - 7) ? ub * 7 : (HH - 7);  // clamp (dups ok)

        // Load W1x transposed into smem [u][k] (small, L2-cached).
        for (int idx = tid; idx < HH * DD; idx += NTHR)
            sW[idx] = W1x[(idx & 63) * HH + (idx >> 6)];

        float bj[7];
        #pragma unroll
        for (int j = 0; j < 7; ++j) bj[j] = B1[u_base + j];

        for (int rt = 0; rt < ROWS * 8; ++rt) {        // 4 rows x 8 t-tiles
            const int row = rt >> 3, tile = rt & 7;
            const int t0  = tile * 64;
            __syncthreads();                            // sXT free (prev reads done)
            // Load x tile: 64t x 64k contiguous -> padded smem rows.
            {
                const float4* xs = reinterpret_cast<const float4*>(
                    X + ((size_t)(r0 + row) * TT + t0) * DD);
                #pragma unroll
                for (int s = 0; s < 4; ++s) {
                    int idx = tid + NTHR * s;          // 0..1023
                    float4 v = xs[idx];
                    *reinterpret_cast<float4*>(&sXT[(idx >> 4) * XPAD + (idx & 15) * 4]) = v;
                }
            }
            __syncthreads();

            unsigned long long acc[4][7];
            #pragma unroll
            for (int i = 0; i < 4; ++i)
                #pragma unroll
                for (int j = 0; j < 7; ++j) acc[i][j] = 0ull;

            #pragma unroll
            for (int kq = 0; kq < 16; ++kq) {
                ulonglong2 xv[4];
                #pragma unroll
                for (int i = 0; i < 4; ++i)             // t = tb + 16i: conflict-free
                    xv[i] = lds128(&sXT[(tb + 16 * i) * XPAD + kq * 4]);
                ulonglong2 wv[7];
                #pragma unroll
                for (int j = 0; j < 7; ++j)             // broadcast within half-warp
                    wv[j] = lds128(&sW[(u_base + j) * DD + kq * 4]);
                #pragma unroll
                for (int i = 0; i < 4; ++i) {
                    #pragma unroll
                    for (int j = 0; j < 7; ++j) {
                        ffma2(acc[i][j], xv[i].x, wv[j].x);
                        ffma2(acc[i][j], xv[i].y, wv[j].y);
                    }
                }
            }

            // Store: XPbuf[b][u][t]; per (j,i): 16 lanes write 16 consec t.
            #pragma unroll
            for (int j = 0; j < 7; ++j) {
                float* dst = &XPbuf[((size_t)(r0 + row) * HH + u_base + j) * TT + t0];
                #pragma unroll
                for (int i = 0; i < 4; ++i)
                    dst[tb + 16 * i] = hsum2(acc[i][j]) + bj[j];
            }
        }
    }
    __syncthreads();

    // ───────────── Phase 1: recurrence (proven structure) ─────────────
    float* sH1 = SM;                            // [2][ROWS][HSR]
    float* sH2 = SM + 2 * ROWS * HSR;
    float* sP  = SM + 4 * ROWS * HSR;

    const int gid  = (wid < 4) ? 0 : ((wid < 6) ? 1 : 2);
    const int uh   = wid & 1;
    const int u0r  = uh * 64 + 2 * lane;
    const bool act = (u0r < HH);
    const int u0   = act ? u0r : (HH - 2);
    const int rp   = (wid >> 1) & 1;

    unsigned long long w[100];
    float bj0 = 0.f, bj1 = 0.f;
    {
        const float* Wsrc = (gid == 0) ? W1h : ((gid == 1) ? W2x : W2h);
        #pragma unroll
        for (int q = 0; q < 25; ++q) {
            int k = 4 * q;
            w[4*q+0] = pack2(Wsrc[(k  )*HH + u0  ], Wsrc[(k+1)*HH + u0  ]);
            w[4*q+1] = pack2(Wsrc[(k+2)*HH + u0  ], Wsrc[(k+3)*HH + u0  ]);
            w[4*q+2] = pack2(Wsrc[(k  )*HH + u0+1], Wsrc[(k+1)*HH + u0+1]);
            w[4*q+3] = pack2(Wsrc[(k+2)*HH + u0+1], Wsrc[(k+3)*HH + u0+1]);
        }
        if (gid == 1) { bj0 = B2[u0]; bj1 = B2[u0 + 1]; }
    }

    // Zero rings.
    for (int idx = tid; idx < 6 * ROWS * HSR; idx += NTHR) SM[idx] = 0.f;
    __syncthreads();

    // G1: XP stream pointers ([b][u][t]: sequential in t) + preload xp_0.
    const float* xpP0 = nullptr; const float* xpP1 = nullptr;
    const float* xpP2 = nullptr; const float* xpP3 = nullptr;
    float2 xcur[2];
    if (gid == 0) {
        xpP0 = &XPbuf[((size_t)(r0 + rp*2    ) * HH + u0    ) * TT];
        xpP1 = &XPbuf[((size_t)(r0 + rp*2    ) * HH + u0 + 1) * TT];
        xpP2 = &XPbuf[((size_t)(r0 + rp*2 + 1) * HH + u0    ) * TT];
        xpP3 = &XPbuf[((size_t)(r0 + rp*2 + 1) * HH + u0 + 1) * TT];
        xcur[0].x = xpP0[0]; xcur[0].y = xpP1[0];
        xcur[1].x = xpP2[0]; xcur[1].y = xpP3[0];
    }

    for (int i = 0; i <= TT + 1; ++i) {
        const int pc = i & 1, pn = pc ^ 1;
        if (gid == 0) {
            if (i <= TT - 1) {                           // h1_i (2 rows)
                float2 xn[2];
                const bool pf = (i + 1 <= TT - 1);
                if (pf) {
                    xn[0].x = xpP0[i+1]; xn[0].y = xpP1[i+1];
                    xn[1].x = xpP2[i+1]; xn[1].y = xpP3[i+1];
                }
                unsigned long long a[4] = {0ull, 0ull, 0ull, 0ull};
                accum4_g1(a, sH1 + pn * ROWS * HSR + (rp*2) * HSR, w);
                if (act) {
                    float2 o0, o1;
                    o0.x = tanh_f(hsum2(a[0]) + xcur[0].x);
                    o0.y = tanh_f(hsum2(a[2]) + xcur[0].y);
                    o1.x = tanh_f(hsum2(a[1]) + xcur[1].x);
                    o1.y = tanh_f(hsum2(a[3]) + xcur[1].y);
                    *reinterpret_cast<float2*>(&sH1[(pc*ROWS + rp*2    ) * HSR + u0]) = o0;
                    *reinterpret_cast<float2*>(&sH1[(pc*ROWS + rp*2 + 1) * HSR + u0]) = o1;
                }
                if (pf) { xcur[0] = xn[0]; xcur[1] = xn[1]; }
            }
            BAR_SYNC(2, 192);
        } else if (gid == 1) {
            if (i >= 1 && i <= TT) {                     // p_{i-1} (4 rows)
                unsigned long long a[8];
                #pragma unroll
                for (int n = 0; n < 8; ++n) a[n] = 0ull;
                accum8_h(a, sH1 + pn * ROWS * HSR, w);
                if (act) {
                    #pragma unroll
                    for (int r = 0; r < ROWS; ++r) {
                        float2 v;
                        v.x = hsum2(a[r])   + bj0;
                        v.y = hsum2(a[4+r]) + bj1;
                        *reinterpret_cast<float2*>(&sP[(pn*ROWS + r) * HSR + u0]) = v;
                    }
                }
            }
            BAR_SYNC(3, 128);   // release G2b first (longer consumer chain)
            BAR_SYNC(2, 192);
        } else {
            if (i >= 2) {                                // h2_{i-2} (4 rows)
                float2 pv[4];
                #pragma unroll
                for (int r = 0; r < ROWS; ++r)
                    pv[r] = *reinterpret_cast<const float2*>(&sP[(pc*ROWS + r) * HSR + u0]);
                unsigned long long a[8];
                #pragma unroll
                for (int n = 0; n < 8; ++n) a[n] = 0ull;
                accum8_h(a, sH2 + pn * ROWS * HSR, w);
                if (act) {
                    #pragma unroll
                    for (int r = 0; r < ROWS; ++r) {
                        float2 v;
                        v.x = tanh_f(hsum2(a[r])   + pv[r].x);
                        v.y = tanh_f(hsum2(a[4+r]) + pv[r].y);
                        *reinterpret_cast<float2*>(&sH2[(pc*ROWS + r) * HSR + u0]) = v;
                    }
                }
            }
            BAR_SYNC(3, 128);
        }
    }
    __syncthreads();

    // h1_511 in sH1 parity 1, h2_511 in sH2 parity 1.
    float* outVec = out;                      // [512]
    float* outH1  = out + BB;                 // [512,100]
    float* outH2  = out + BB + BB*HH;         // [512,100]

    for (int idx = tid; idx < ROWS*HH; idx += NTHR) {
        int r = idx / HH, uu = idx % HH;
        outH1[(size_t)(r0 + r)*HH + uu] = sH1[(ROWS + r) * HSR + uu];
        outH2[(size_t)(r0 + r)*HH + uu] = sH2[(ROWS + r) * HSR + uu];
    }

    // Output head: out[r] = h2_T[r] . Wo + bo  (warp 0).
    if (tid < 32) {
        #pragma unroll
        for (int r = 0; r < ROWS; ++r) {
            float v = 0.f;
            #pragma unroll
            for (int mm = 0; mm < 4; ++mm) {
                int uu = mm*32 + tid;
                if (uu < HH) v += sH2[(ROWS + r) * HSR + uu] * Wo[uu];
            }
            #pragma unroll
            for (int off = 16; off; off >>= 1)
                v += __shfl_down_sync(0xffffffffu, v, off);
            if (tid == 0) outVec[r0 + r] = v + Bo[0];
        }
    }
}

extern "C" void kernel_launch(void* const* d_in, const int* in_sizes, int n_in,
                              void* d_out, int out_size) {
    (void)in_sizes; (void)n_in; (void)out_size;
    const float* X   = (const float*)d_in[0];
    const float* W1x = (const float*)d_in[1];
    const float* W1h = (const float*)d_in[2];
    const float* B1  = (const float*)d_in[3];
    const float* W2x = (const float*)d_in[4];
    const float* W2h = (const float*)d_in[5];
    const float* B2  = (const float*)d_in[6];
    const float* Wo  = (const float*)d_in[7];
    const float* Bo  = (const float*)d_in[8];

    drnn_kernel<<<BB/ROWS, NTHR>>>(X, W1x, B1, W1h, W2x, W2h, B2, Wo, Bo,
                                   (float*)d_out);
}

// round 17
// speedup vs baseline: 1.1910x; 1.1293x over previous
#include <cuda_runtime.h>

// DRNN: two stacked SimpleRNN(tanh), round 14. B=512, T=512, D=64, H=100.
//
// Kernel 1 (xp_prepass v6): XP[b][t][u] = x_{b,t}.W1x[:,u] + b1[u].
//   Engineered against ALL diagnosed prepass failures:
//   - no spills: 4t x 4u tile, both operands from smem -> ~85 regs < 100 cap
//     (launch_bounds(256,2) -> 2 CTAs/SM, 4 warps/SMSP)
//   - 1:4 LDS:FFMA2 (8 LDS.128 -> 32 FFMA2 per k-quad), 16 indep chains
//   - conflict-free: W rows padded to 68 floats (17 quads === 1 mod 8
//     quad-banks -> 16 ub-lanes spread); x reads are 2-line broadcasts
//   - coalesced stores: u = ub + 16j -> 16 lanes write 64B runs in [b][t][u]
//   - u-dim split over 2 CTAs (grid 16x512, 50u each; edge clamp = benign
//     duplicate same-value stores)
//
// Kernel 2 (mainloop): BYTE-IDENTICAL to the proven-627us R12 kernel:
//   128 CTAs x 4 rows, 256 thr, all warps 2 units/lane (100 u64 wregs),
//   600 LDS/step, 600 FFMA2/SMSP balanced (1200-cyc floor):
//   G1 (wid 0-3) row-split 2 rows/warp; G2a (wid 4,5); G2b (wid 6,7).
//   Pairwise named barriers bar2 (G1+G2a), bar3 (G2a+G2b).

#define TT   512
#define BB   512
#define DD   64
#define HH   100
#define ROWS 4
#define HSR  104    // h/p row stride (mainloop rings)
#define NTHR 256
#define WPAD 68     // prepass smem row stride: 17 quads === 1 (mod 8) -> spread

#define BAR_SYNC(id, cnt) asm volatile("bar.sync %0, %1;" :: "r"(id), "r"(cnt) : "memory")

__device__ float XPbuf[(size_t)BB * TT * HH];   // [b][t][u], 104.8 MB

__device__ __forceinline__ void ffma2(unsigned long long &acc,
                                      unsigned long long a,
                                      unsigned long long b) {
    asm("fma.rn.f32x2 %0, %1, %2, %0;" : "+l"(acc) : "l"(a), "l"(b));
}

__device__ __forceinline__ unsigned long long pack2(float lo, float hi) {
    unsigned long long r;
    asm("mov.b64 %0, {%1, %2};" : "=l"(r) : "f"(lo), "f"(hi));
    return r;
}

__device__ __forceinline__ float hsum2(unsigned long long v) {
    float lo, hi;
    asm("mov.b64 {%0, %1}, %2;" : "=f"(lo), "=f"(hi) : "l"(v));
    return lo + hi;
}

__device__ __forceinline__ ulonglong2 lds128(const float* p) {
    return *reinterpret_cast<const ulonglong2*>(p);
}

// tanh via exp + fast divide: ~1e-7 rel err.
__device__ __forceinline__ float tanh_f(float x) {
    float ax = fabsf(x);
    float e  = __expf(-2.0f * ax);
    float r  = __fdividef(1.0f - e, 1.0f + e);
    return copysignf(r, x);
}

// ───────────────────────── Kernel 1: XP pre-pass v6 ──────────────────────
// grid (16, 512): bx>>1 = 64-t tile (0..7), bx&1 = u-half (0..1); by = b.
// 256 thr: ub = tid&15, tg = tid>>4. Thread tile: t = 4tg+i (i<4),
// u = min(ub+16j, 49) (j<4, clamp dups benign). Both operands from smem.
__global__ __launch_bounds__(256, 2)
void xp_prepass(const float* __restrict__ X, const float* __restrict__ W1x,
                const float* __restrict__ B1)
{
    __shared__ __align__(16) float sW [50 * WPAD];   // 13600 B, [u][k] padded
    __shared__ __align__(16) float sXT[64 * WPAD];   // 17408 B, [t][k] padded

    const int b     = blockIdx.y;
    const int t0    = (blockIdx.x >> 1) * 64;
    const int u_off = (blockIdx.x & 1) * 50;
    const int tid   = threadIdx.x;
    const int ub    = tid & 15;
    const int tg    = tid >> 4;

    // Load W half, transposed into padded rows (gmem reads in 50-float runs).
    for (int idx = tid; idx < DD * 50; idx += NTHR) {
        int k = idx / 50, u = idx % 50;
        sW[u * WPAD + k] = W1x[k * HH + u_off + u];
    }
    // Load x tile: 64t x 64k contiguous float4.
    {
        const float4* xs = reinterpret_cast<const float4*>(
            X + ((size_t)b * TT + t0) * DD);
        #pragma unroll
        for (int s = 0; s < 4; ++s) {
            int idx = tid + NTHR * s;              // 0..1023
            float4 v = xs[idx];
            *reinterpret_cast<float4*>(&sXT[(idx >> 4) * WPAD + (idx & 15) * 4]) = v;
        }
    }
    __syncthreads();

    int   uj[4];
    float bj[4];
    #pragma unroll
    for (int j = 0; j < 4; ++j) {
        int u = ub + 16 * j;
        uj[j] = (u < 50) ? u : 49;                 // clamp (dup writes benign)
        bj[j] = B1[u_off + uj[j]];
    }

    unsigned long long acc[4][4];
    #pragma unroll
    for (int i = 0; i < 4; ++i)
        #pragma unroll
        for (int j = 0; j < 4; ++j) acc[i][j] = 0ull;

    #pragma unroll
    for (int kq = 0; kq < 16; ++kq) {
        ulonglong2 xv[4];
        #pragma unroll
        for (int i = 0; i < 4; ++i)                // 2 bcast lines per warp
            xv[i] = lds128(&sXT[(4 * tg + i) * WPAD + kq * 4]);
        ulonglong2 wv[4];
        #pragma unroll
        for (int j = 0; j < 4; ++j)                // 16 lanes spread (stride 17q)
            wv[j] = lds128(&sW[uj[j] * WPAD + kq * 4]);
        #pragma unroll
        for (int i = 0; i < 4; ++i) {
            #pragma unroll
            for (int j = 0; j < 4; ++j) {
                ffma2(acc[i][j], xv[i].x, wv[j].x);
                ffma2(acc[i][j], xv[i].y, wv[j].y);
            }
        }
    }

    // Stores: for fixed (i,j), 16 ub-lanes write consecutive u -> 64B runs.
    #pragma unroll
    for (int i = 0; i < 4; ++i) {
        float* dst = &XPbuf[((size_t)b * TT + t0 + 4 * tg + i) * HH + u_off];
        #pragma unroll
        for (int j = 0; j < 4; ++j)
            dst[uj[j]] = hsum2(acc[i][j]) + bj[j];
    }
}

// ───────────────────────── Kernel 2: main recurrence (proven 627us) ──────

// G2 accumulate: 4 rows x 2 units. acc[r]=unit0, acc[4+r]=unit1.
__device__ __forceinline__ void accum8_h(unsigned long long (&acc)[8],
                                         const float* base,
                                         const unsigned long long* w)
{
    #pragma unroll
    for (int it = 0; it < 25; ++it) {
        ulonglong2 v0 = lds128(base + 0*HSR + 4*it);
        ulonglong2 v1 = lds128(base + 1*HSR + 4*it);
        ulonglong2 v2 = lds128(base + 2*HSR + 4*it);
        ulonglong2 v3 = lds128(base + 3*HSR + 4*it);
        unsigned long long wA0 = w[4*it + 0];
        unsigned long long wB0 = w[4*it + 1];
        unsigned long long wA1 = w[4*it + 2];
        unsigned long long wB1 = w[4*it + 3];
        ffma2(acc[0], v0.x, wA0); ffma2(acc[4], v0.x, wA1);
        ffma2(acc[1], v1.x, wA0); ffma2(acc[5], v1.x, wA1);
        ffma2(acc[2], v2.x, wA0); ffma2(acc[6], v2.x, wA1);
        ffma2(acc[3], v3.x, wA0); ffma2(acc[7], v3.x, wA1);
        ffma2(acc[0], v0.y, wB0); ffma2(acc[4], v0.y, wB1);
        ffma2(acc[1], v1.y, wB0); ffma2(acc[5], v1.y, wB1);
        ffma2(acc[2], v2.y, wB0); ffma2(acc[6], v2.y, wB1);
        ffma2(acc[3], v3.y, wB0); ffma2(acc[7], v3.y, wB1);
    }
}

// G1 accumulate: 2 rows x 2 units. acc = {r0u0, r1u0, r0u1, r1u1}.
__device__ __forceinline__ void accum4_g1(unsigned long long (&acc)[4],
                                          const float* base,
                                          const unsigned long long* w)
{
    #pragma unroll
    for (int it = 0; it < 25; ++it) {
        ulonglong2 v0 = lds128(base + 0*HSR + 4*it);
        ulonglong2 v1 = lds128(base + 1*HSR + 4*it);
        unsigned long long wA0 = w[4*it + 0];
        unsigned long long wB0 = w[4*it + 1];
        unsigned long long wA1 = w[4*it + 2];
        unsigned long long wB1 = w[4*it + 3];
        ffma2(acc[0], v0.x, wA0); ffma2(acc[1], v1.x, wA0);
        ffma2(acc[2], v0.x, wA1); ffma2(acc[3], v1.x, wA1);
        ffma2(acc[0], v0.y, wB0); ffma2(acc[1], v1.y, wB0);
        ffma2(acc[2], v0.y, wB1); ffma2(acc[3], v1.y, wB1);
    }
}

__global__ __launch_bounds__(NTHR, 1)
void drnn_kernel(const float* __restrict__ W1h,
                 const float* __restrict__ W2x, const float* __restrict__ W2h,
                 const float* __restrict__ B2,
                 const float* __restrict__ Wo,  const float* __restrict__ Bo,
                 float* __restrict__ out)
{
    __shared__ __align__(16) float sH1[2][ROWS][HSR];
    __shared__ __align__(16) float sH2[2][ROWS][HSR];
    __shared__ __align__(16) float sP [2][ROWS][HSR];   // p = W2x.h1 + b2

    const int tid  = threadIdx.x;
    const int wid  = tid >> 5;
    const int lane = tid & 31;
    const int r0   = blockIdx.x * ROWS;
    const int gid  = (wid < 4) ? 0 : ((wid < 6) ? 1 : 2);
    const int uh   = wid & 1;
    const int u0r  = uh * 64 + 2 * lane;
    const bool act = (u0r < HH);
    const int u0   = act ? u0r : (HH - 2);
    const int rp   = (wid >> 1) & 1;

    unsigned long long w[100];
    float bj0 = 0.f, bj1 = 0.f;
    {
        const float* Wsrc = (gid == 0) ? W1h : ((gid == 1) ? W2x : W2h);
        #pragma unroll
        for (int q = 0; q < 25; ++q) {
            int k = 4 * q;
            w[4*q+0] = pack2(Wsrc[(k  )*HH + u0  ], Wsrc[(k+1)*HH + u0  ]);
            w[4*q+1] = pack2(Wsrc[(k+2)*HH + u0  ], Wsrc[(k+3)*HH + u0  ]);
            w[4*q+2] = pack2(Wsrc[(k  )*HH + u0+1], Wsrc[(k+1)*HH + u0+1]);
            w[4*q+3] = pack2(Wsrc[(k+2)*HH + u0+1], Wsrc[(k+3)*HH + u0+1]);
        }
        if (gid == 1) { bj0 = B2[u0]; bj1 = B2[u0 + 1]; }
    }

    {
        float* z1 = &sH1[0][0][0];
        for (int idx = tid; idx < 2*ROWS*HSR; idx += NTHR) z1[idx] = 0.f;
        float* z2 = &sH2[0][0][0];
        for (int idx = tid; idx < 2*ROWS*HSR; idx += NTHR) z2[idx] = 0.f;
    }
    __syncthreads();

    float2 xcur[2];
    if (gid == 0) {
        #pragma unroll
        for (int r = 0; r < 2; ++r)
            xcur[r] = *reinterpret_cast<const float2*>(
                &XPbuf[((size_t)(r0 + rp*2 + r) * TT + 0) * HH + u0]);
    }

    for (int i = 0; i <= TT + 1; ++i) {
        const int pc = i & 1, pn = pc ^ 1;
        if (gid == 0) {
            if (i <= TT - 1) {                           // h1_i (2 rows)
                float2 xn[2];
                const bool pf = (i + 1 <= TT - 1);
                if (pf) {
                    #pragma unroll
                    for (int r = 0; r < 2; ++r)
                        xn[r] = *reinterpret_cast<const float2*>(
                            &XPbuf[((size_t)(r0 + rp*2 + r) * TT + (i+1)) * HH + u0]);
                }
                unsigned long long a[4] = {0ull, 0ull, 0ull, 0ull};
                accum4_g1(a, &sH1[pn][rp*2][0], w);
                if (act) {
                    float2 o0, o1;
                    o0.x = tanh_f(hsum2(a[0]) + xcur[0].x);
                    o0.y = tanh_f(hsum2(a[2]) + xcur[0].y);
                    o1.x = tanh_f(hsum2(a[1]) + xcur[1].x);
                    o1.y = tanh_f(hsum2(a[3]) + xcur[1].y);
                    *reinterpret_cast<float2*>(&sH1[pc][rp*2    ][u0]) = o0;
                    *reinterpret_cast<float2*>(&sH1[pc][rp*2 + 1][u0]) = o1;
                }
                if (pf) { xcur[0] = xn[0]; xcur[1] = xn[1]; }
            }
            BAR_SYNC(2, 192);
        } else if (gid == 1) {
            if (i >= 1 && i <= TT) {                     // p_{i-1} (4 rows)
                unsigned long long a[8];
                #pragma unroll
                for (int n = 0; n < 8; ++n) a[n] = 0ull;
                accum8_h(a, &sH1[pn][0][0], w);
                if (act) {
                    #pragma unroll
                    for (int r = 0; r < ROWS; ++r) {
                        float2 v;
                        v.x = hsum2(a[r])   + bj0;
                        v.y = hsum2(a[4+r]) + bj1;
                        *reinterpret_cast<float2*>(&sP[pn][r][u0]) = v;
                    }
                }
            }
            BAR_SYNC(3, 128);   // release G2b first (longer consumer chain)
            BAR_SYNC(2, 192);
        } else {
            if (i >= 2) {                                // h2_{i-2} (4 rows)
                float2 pv[4];
                #pragma unroll
                for (int r = 0; r < ROWS; ++r)
                    pv[r] = *reinterpret_cast<const float2*>(&sP[pc][r][u0]);
                unsigned long long a[8];
                #pragma unroll
                for (int n = 0; n < 8; ++n) a[n] = 0ull;
                accum8_h(a, &sH2[pn][0][0], w);
                if (act) {
                    #pragma unroll
                    for (int r = 0; r < ROWS; ++r) {
                        float2 v;
                        v.x = tanh_f(hsum2(a[r])   + pv[r].x);
                        v.y = tanh_f(hsum2(a[4+r]) + pv[r].y);
                        *reinterpret_cast<float2*>(&sH2[pc][r][u0]) = v;
                    }
                }
            }
            BAR_SYNC(3, 128);
        }
    }
    __syncthreads();

    float* outVec = out;                      // [512]
    float* outH1  = out + BB;                 // [512,100]
    float* outH2  = out + BB + BB*HH;         // [512,100]

    for (int idx = tid; idx < ROWS*HH; idx += NTHR) {
        int r = idx / HH, uu = idx % HH;
        outH1[(size_t)(r0 + r)*HH + uu] = sH1[1][r][uu];
        outH2[(size_t)(r0 + r)*HH + uu] = sH2[1][r][uu];
    }

    if (tid < 32) {
        #pragma unroll
        for (int r = 0; r < ROWS; ++r) {
            float v = 0.f;
            #pragma unroll
            for (int mm = 0; mm < 4; ++mm) {
                int uu = mm*32 + tid;
                if (uu < HH) v += sH2[1][r][uu] * Wo[uu];
            }
            #pragma unroll
            for (int off = 16; off; off >>= 1)
                v += __shfl_down_sync(0xffffffffu, v, off);
            if (tid == 0) outVec[r0 + r] = v + Bo[0];
        }
    }
}

extern "C" void kernel_launch(void* const* d_in, const int* in_sizes, int n_in,
                              void* d_out, int out_size) {
    (void)in_sizes; (void)n_in; (void)out_size;
    const float* X   = (const float*)d_in[0];
    const float* W1x = (const float*)d_in[1];
    const float* W1h = (const float*)d_in[2];
    const float* B1  = (const float*)d_in[3];
    const float* W2x = (const float*)d_in[4];
    const float* W2h = (const float*)d_in[5];
    const float* B2  = (const float*)d_in[6];
    const float* Wo  = (const float*)d_in[7];
    const float* Bo  = (const float*)d_in[8];

    dim3 pgrid(16, BB);
    xp_prepass<<<pgrid, 256>>>(X, W1x, B1);
    drnn_kernel<<<BB/ROWS, NTHR>>>(W1h, W2x, W2h, B2, Wo, Bo, (float*)d_out);
}